// round 13
// baseline (speedup 1.0000x reference)
#include <cuda_runtime.h>
#include <cuda_fp16.h>
#include <math.h>
#include <stdint.h>

// Problem constants
#define NN 48
#define CC 512
#define PP 1600      // 40*40
#define KK 64
#define KC 32768     // K*C
#define NPT 25       // P / 64 tiles (k_assign)
#define NSPLIT 3     // split-P factor for GEMM2

// ---------------- scratch ---------------------------------------------------
__device__ __align__(256) __half g_w2f[(size_t)NN * PP * KK];  // w2 fp16 [n][p][k]
__device__ float g_wsp [NN * NPT * KK];          // partial wsum [n][pt][k]
__device__ __align__(256) __half g_cwF[CC * KK]; // conv_w^T fp16 [c][k]
__device__ float g_gpart[NN * KK];
__device__ float g_vp  [(size_t)NSPLIT * NN * KK * CC];  // GEMM2 partials

// ---------------- helpers ----------------------------------------------------
__device__ __forceinline__ uint32_t s2u32(const void* p) {
    uint32_t a;
    asm("{ .reg .u64 t; cvta.to.shared.u64 t, %1; cvt.u32.u64 %0, t; }" : "=r"(a) : "l"(p));
    return a;
}
__device__ __forceinline__ void cpa16(uint32_t d, const void* s) {
    asm volatile("cp.async.cg.shared.global [%0], [%1], 16;" :: "r"(d), "l"(s) : "memory");
}
#define CP_COMMIT() asm volatile("cp.async.commit_group;" ::: "memory")
#define CP_WAIT(n)  asm volatile("cp.async.wait_group %0;" :: "n"(n) : "memory")

#define LDSM4(r0,r1,r2,r3,addr) \
    asm volatile("ldmatrix.sync.aligned.m8n8.x4.shared.b16 {%0,%1,%2,%3}, [%4];" \
                 : "=r"(r0), "=r"(r1), "=r"(r2), "=r"(r3) : "r"(addr))
#define LDSM4T(r0,r1,r2,r3,addr) \
    asm volatile("ldmatrix.sync.aligned.m8n8.x4.trans.shared.b16 {%0,%1,%2,%3}, [%4];" \
                 : "=r"(r0), "=r"(r1), "=r"(r2), "=r"(r3) : "r"(addr))
#define LDSM2T(r0,r1,addr) \
    asm volatile("ldmatrix.sync.aligned.m8n8.x2.trans.shared.b16 {%0,%1}, [%2];" \
                 : "=r"(r0), "=r"(r1) : "r"(addr))
#define MMAH(d, a, b0, b1) \
    asm volatile("mma.sync.aligned.m16n8k16.row.col.f32.f16.f16.f32 " \
                 "{%0,%1,%2,%3}, {%4,%5,%6,%7}, {%8,%9}, {%0,%1,%2,%3};" \
                 : "+f"((d)[0]), "+f"((d)[1]), "+f"((d)[2]), "+f"((d)[3]) \
                 : "r"((a)[0]), "r"((a)[1]), "r"((a)[2]), "r"((a)[3]), "r"(b0), "r"(b1))

__device__ __forceinline__ uint32_t packh(float a, float b) {
    __half2 h = __floats2half2_rn(a, b);
    return *reinterpret_cast<uint32_t*>(&h);
}

// ---------------- kernel P: transpose + fp16 conv_w -------------------------
__global__ void k_transpose(const float* __restrict__ conv_w) {
    int i = blockIdx.x * 256 + threadIdx.x;   // i = c*64 + k
    if (i < CC * KK) {
        int c = i >> 6, k = i & 63;
        g_cwF[i] = __float2half_rn(conv_w[k * CC + c]);
    }
}

// ---------------- kernel B: GEMM1 fp16 mma, 256 thr, register prep ----------
// CTA tile [k=64][p=64], 8 warps x (k64, p8) each, kdim = C in 32 chunks of 16.
// A = conv_w [c][k] fp16, LDSM4T. B = x chunk [c][p] fp16, LDSM2T.
// ss/hs prep accumulated in registers from the conversion loads.
struct AsgG {
    float stgX[2][16][68];               // fp32 x stage (cp.async)
    __half awF[2][16][72];               // conv fp16 tiles [c][k] (cp.async)
    __half xsF[16][72];                  // x fp16 tiles [c][p]
};
struct AsgS {
    float S[64][65];                      // raw logits [p][k]
    float ps[8][64];                      // warp wsum partials
    float rss[16][64];                    // ss partials [cc][p]
    float rhs[16][64];                    // hs partials [cc][p]
};
union AsgU { AsgG g; AsgS s; };

__global__ __launch_bounds__(256, 4) void k_assign_mma(const float* __restrict__ x,
                                                       const float* __restrict__ aw,
                                                       const float* __restrict__ ab) {
    __shared__ __align__(16) AsgU u;
    __shared__ float saw[CC];
    __shared__ float ivb[64], hmb[64];
    int pt = blockIdx.x, n = blockIdx.y;
    int p0 = pt * 64;
    int tid = threadIdx.x;
    int lane = tid & 31, warp = tid >> 5;

    for (int i = tid; i < CC; i += 256) saw[i] = aw[i];

    // ldmatrix lane addressing
    int lr = lane & 7, lg = lane >> 3;
    // A (trans x4 from [c][k]): m0=(c0-7,k0-7) m1=(c0-7,k8-15) m2=(c8-15,k0-7) m3=(c8-15,k8-15)
    int aRow = ((lg & 2) ? 8 : 0) + lr, aCol = (lg & 1) ? 8 : 0;
    uint32_t aF[2] = { s2u32(&u.g.awF[0][aRow][aCol]), s2u32(&u.g.awF[1][aRow][aCol]) };
    // B (trans x2 from [c][p]): lanes 0-15 -> rows c0-15, cols = warp's p8
    uint32_t bF = s2u32(&u.g.xsF[lane & 15][warp * 8]);

    // staging: thread -> (row cc, float4 at pq)
    int cc = tid >> 4, pq = (tid & 15) * 4;
    const float* xsrc = x + ((size_t)(n * CC) + cc) * PP + p0 + pq;
    int ar = tid >> 3, ac = (tid & 7) * 8;   // conv tile mapping (threads < 128)

#define AISSUE(ch, b) do {                                                     \
        int _c0 = (ch) * 16;                                                   \
        cpa16(s2u32(&u.g.stgX[b][cc][pq]), xsrc + (size_t)_c0 * PP);           \
        if (tid < 128)                                                         \
            cpa16(s2u32(&u.g.awF[b][ar][ac]), g_cwF + (_c0 + ar) * KK + ac);   \
    } while (0)

    float d[4][4] = {};
    float ssp[4] = {}, hsp[4] = {};

    AISSUE(0, 0); CP_COMMIT();
    for (int ch = 0; ch < 32; ch++) {
        int b = ch & 1;
        if (ch < 31) { AISSUE(ch + 1, b ^ 1); CP_COMMIT(); CP_WAIT(1); }
        else CP_WAIT(0);
        // convert OWN staged float4 to fp16 AND accumulate prep in registers
        {
            float4 v = *reinterpret_cast<float4*>(&u.g.stgX[b][cc][pq]);
            float sw = saw[ch * 16 + cc];
            ssp[0] += v.x * v.x; hsp[0] += fmaxf(v.x, 0.f) * sw;
            ssp[1] += v.y * v.y; hsp[1] += fmaxf(v.y, 0.f) * sw;
            ssp[2] += v.z * v.z; hsp[2] += fmaxf(v.z, 0.f) * sw;
            ssp[3] += v.w * v.w; hsp[3] += fmaxf(v.w, 0.f) * sw;
            uint2 hv = make_uint2(packh(v.x, v.y), packh(v.z, v.w));
            *reinterpret_cast<uint2*>(&u.g.xsF[cc][pq]) = hv;
        }
        __syncthreads();
        uint32_t b0, b1;
        LDSM2T(b0, b1, bF);
#pragma unroll
        for (int mt = 0; mt < 4; mt++) {
            uint32_t ah[4];
            LDSM4T(ah[0], ah[1], ah[2], ah[3], aF[b] + mt * 32);
            MMAH(d[mt], ah, b0, b1);
        }
        __syncthreads();
    }

    // epilogue: S[p][k] from fragments + prep partials to smem
    int grp = lane >> 2, q = lane & 3;
#pragma unroll
    for (int mt = 0; mt < 4; mt++) {
        int p = warp * 8 + q * 2;
        int k = mt * 16 + grp;
        u.s.S[p][k]         = d[mt][0];
        u.s.S[p + 1][k]     = d[mt][1];
        u.s.S[p][k + 8]     = d[mt][2];
        u.s.S[p + 1][k + 8] = d[mt][3];
    }
#pragma unroll
    for (int j = 0; j < 4; j++) {
        u.s.rss[cc][pq + j] = ssp[j];
        u.s.rhs[cc][pq + j] = hsp[j];
    }
    __syncthreads();
    if (tid < 64) {
        float st = 0.f, ht = 0.f;
#pragma unroll
        for (int c = 0; c < 16; c++) { st += u.s.rss[c][tid]; ht += u.s.rhs[c][tid]; }
        ivb[tid] = 1.f / fmaxf(sqrtf(st), 1e-12f);
        hmb[tid] = fmaxf(ht + ab[0], 0.f);
    }
    __syncthreads();

    // softmax over k per p-row; 8 warps x 8 rows
    float pa = 0.f, pb = 0.f;
    for (int r8 = 0; r8 < 8; r8++) {
        int r = warp * 8 + r8;
        float iv = ivb[r];
        float v0 = u.s.S[r][lane] * iv;
        float v1 = u.s.S[r][lane + 32] * iv;
        float m = fmaxf(v0, v1);
#pragma unroll
        for (int o = 16; o > 0; o >>= 1) m = fmaxf(m, __shfl_xor_sync(0xffffffffu, m, o));
        float e0 = __expf(v0 - m), e1 = __expf(v1 - m);
        float s = e0 + e1;
#pragma unroll
        for (int o = 16; o > 0; o >>= 1) s += __shfl_xor_sync(0xffffffffu, s, o);
        float h = hmb[r];
        float sc = h / s;
        float w0 = e0 * sc, w1 = e1 * sc;
        size_t base = ((size_t)n * PP + p0 + r) * KK;
        g_w2f[base + lane]      = __float2half_rn(w0 * iv);
        g_w2f[base + lane + 32] = __float2half_rn(w1 * iv);
        pa += w0; pb += w1;
    }
    u.s.ps[warp][lane]      = pa;
    u.s.ps[warp][lane + 32] = pb;
    __syncthreads();
    if (tid < 64) {
        float s = 0.f;
#pragma unroll
        for (int w = 0; w < 8; w++) s += u.s.ps[w][tid];
        g_wsp[(n * NPT + pt) * KK + tid] = s;
    }
}

// ---------------- kernel C: GEMM2 fp16 mma (single product) -----------------
// CTA: (c-tile 128, n, p-split). D[k=64][c=128] = sum_p w2[k][p] * x[c][p].
__global__ __launch_bounds__(128, 4) void k_vlad_mma(const float* __restrict__ x) {
    __shared__ __align__(16) float stgX[2][128][20];      // fp32 x stage
    __shared__ __align__(16) __half xsF[128][24];         // B fp16 tiles [c][p]
    __shared__ __align__(16) __half wsF[2][16][72];       // A^T tiles [p][k]

    int ct = blockIdx.x, n = blockIdx.y, sp = blockIdx.z;
    int c0 = ct * 128;
    int p0  = (sp == 0) ? 0 : 544 + (sp - 1) * 528;
    int nch = (sp == 0) ? 34 : 33;
    int tid = threadIdx.x;
    int lane = tid & 31, warp = tid >> 5;

    int lr = lane & 7, lg = lane >> 3;
    int bRow = warp * 32 + ((lg & 2) ? 8 : 0) + lr;
    int bCol = (lg & 1) ? 8 : 0;
    uint32_t bAF0 = s2u32(&xsF[bRow][bCol]);
    uint32_t bAF1 = s2u32(&xsF[bRow + 16][bCol]);
    int aRow = ((lg & 2) ? 8 : 0) + lr;
    int aColB = (lg & 1) ? 8 : 0;
    uint32_t aAF[2][4];
#pragma unroll
    for (int bb = 0; bb < 2; bb++)
#pragma unroll
        for (int mt = 0; mt < 4; mt++)
            aAF[bb][mt] = s2u32(&wsF[bb][aRow][mt * 16 + aColB]);

    const float* xrow = x + ((size_t)(n * CC + c0 + tid)) * PP + p0;
    int wp = tid >> 3, wk = (tid & 7) * 8;
    size_t wbase = ((size_t)n * PP + p0 + wp) * KK + wk;

#define VISSUE(ci, b) do {                                                     \
        const float* _xp = xrow + (ci) * 16;                                   \
        cpa16(s2u32(&stgX[b][tid][0]),  _xp);                                  \
        cpa16(s2u32(&stgX[b][tid][4]),  _xp + 4);                              \
        cpa16(s2u32(&stgX[b][tid][8]),  _xp + 8);                              \
        cpa16(s2u32(&stgX[b][tid][12]), _xp + 12);                             \
        cpa16(s2u32(&wsF[b][wp][wk]), g_w2f + wbase + (size_t)(ci) * 16 * KK); \
    } while (0)

    float d[4][4][4] = {};

    VISSUE(0, 0); CP_COMMIT();
    for (int i = 0; i < nch; i++) {
        int b = i & 1;
        if (i + 1 < nch) { VISSUE(i + 1, b ^ 1); CP_COMMIT(); CP_WAIT(1); }
        else CP_WAIT(0);
        // convert OWN staged x (16 values) to single fp16
        {
            uint32_t hp[8];
#pragma unroll
            for (int q = 0; q < 4; q++) {
                float4 v = *reinterpret_cast<float4*>(&stgX[b][tid][q * 4]);
                hp[q * 2]     = packh(v.x, v.y);
                hp[q * 2 + 1] = packh(v.z, v.w);
            }
            *reinterpret_cast<uint4*>(&xsF[tid][0]) = make_uint4(hp[0], hp[1], hp[2], hp[3]);
            *reinterpret_cast<uint4*>(&xsF[tid][8]) = make_uint4(hp[4], hp[5], hp[6], hp[7]);
        }
        __syncthreads();
        uint32_t bf[8];
        LDSM4(bf[0], bf[1], bf[2], bf[3], bAF0);
        LDSM4(bf[4], bf[5], bf[6], bf[7], bAF1);
#pragma unroll
        for (int mt = 0; mt < 4; mt++) {
            uint32_t af[4];
            LDSM4T(af[0], af[1], af[2], af[3], aAF[b][mt]);
#pragma unroll
            for (int ng = 0; ng < 4; ng++)
                MMAH(d[mt][ng], af, bf[ng * 2], bf[ng * 2 + 1]);
        }
        __syncthreads();
    }
    int grp = lane >> 2, q = lane & 3;
#pragma unroll
    for (int mt = 0; mt < 4; mt++)
#pragma unroll
        for (int ng = 0; ng < 4; ng++) {
            int k = mt * 16 + grp;
            int c = c0 + warp * 32 + ng * 8 + q * 2;
            size_t o = (((size_t)sp * NN + n) * KK + k) * CC + c;
            *reinterpret_cast<float2*>(&g_vp[o]) =
                make_float2(d[mt][ng][0], d[mt][ng][1]);
            *reinterpret_cast<float2*>(&g_vp[o + 8 * CC]) =
                make_float2(d[mt][ng][2], d[mt][ng][3]);
        }
}

// ---------------- kernel E: reduce partials + residual + intra L2 ----------
__global__ __launch_bounds__(256) void k_norm1(const float* __restrict__ cent,
                                               float* __restrict__ out) {
    __shared__ float red[256];
    int k = blockIdx.x, n = blockIdx.y, tid = threadIdx.x;
    float wsum = 0.f;
#pragma unroll
    for (int t = 0; t < NPT; t++) wsum += g_wsp[(n * NPT + t) * KK + k];

    float t1a = 0.f, t1b = 0.f;
#pragma unroll
    for (int s = 0; s < NSPLIT; s++) {
        size_t b = (((size_t)s * NN + n) * KK + k) * CC;
        t1a += g_vp[b + tid];
        t1b += g_vp[b + tid + 256];
    }
    size_t base = (size_t)n * KC + (size_t)k * CC;
    float v1 = t1a - wsum * cent[k * CC + tid];
    float v2 = t1b - wsum * cent[k * CC + tid + 256];
    red[tid] = v1 * v1 + v2 * v2;
    __syncthreads();
    for (int o = 128; o > 0; o >>= 1) {
        if (tid < o) red[tid] += red[tid + o];
        __syncthreads();
    }
    float tot = red[0];
    float inv = 1.f / fmaxf(sqrtf(tot), 1e-12f);
    out[base + tid]       = v1 * inv;
    out[base + tid + 256] = v2 * inv;
    if (tid == 0) g_gpart[n * KK + k] = tot * inv * inv;
}

// ---------------- kernel F: global L2 normalize ------------------------------
__global__ __launch_bounds__(256) void k_norm2(float* __restrict__ out) {
    __shared__ float s[KK];
    __shared__ float ginv;
    size_t i = (size_t)blockIdx.x * 256 + threadIdx.x;
    int n = (int)(i >> 15);
    if (threadIdx.x < KK) s[threadIdx.x] = g_gpart[n * KK + threadIdx.x];
    __syncthreads();
    if (threadIdx.x == 0) {
        float t = 0.f;
#pragma unroll
        for (int j = 0; j < KK; j++) t += s[j];
        ginv = 1.f / fmaxf(sqrtf(t), 1e-12f);
    }
    __syncthreads();
    out[i] *= ginv;
}

// ---------------- launch -----------------------------------------------------
extern "C" void kernel_launch(void* const* d_in, const int* in_sizes, int n_in,
                              void* d_out, int out_size) {
    const float* x      = (const float*)d_in[0];
    const float* conv_w = (const float*)d_in[1];
    const float* attn_w = (const float*)d_in[2];
    const float* attn_b = (const float*)d_in[3];
    const float* cent   = (const float*)d_in[4];
    float* out = (float*)d_out;
    (void)in_sizes; (void)n_in; (void)out_size;

    k_transpose<<<(CC * KK + 255) / 256, 256>>>(conv_w);
    k_assign_mma<<<dim3(NPT, NN), 256>>>(x, attn_w, attn_b);
    k_vlad_mma<<<dim3(4, NN, NSPLIT), 128>>>(x);
    k_norm1<<<dim3(KK, NN), 256>>>(cent, out);
    k_norm2<<<(NN * KC) / 256, 256>>>(out);
}

// round 14
// speedup vs baseline: 1.4202x; 1.4202x over previous
#include <cuda_runtime.h>
#include <cuda_fp16.h>
#include <math.h>
#include <stdint.h>

// Problem constants
#define NN 48
#define CC 512
#define PP 1600      // 40*40
#define KK 64
#define KC 32768     // K*C
#define NPT 25       // P / 64 tiles (k_assign)
#define NSPLIT 3     // split-P factor for GEMM2

// ---------------- scratch ---------------------------------------------------
__device__ __align__(256) __half g_w2f[(size_t)NN * PP * KK];  // w2 fp16 [n][p][k]
__device__ float g_wsp [NN * NPT * KK];          // partial wsum [n][pt][k]
__device__ __align__(256) __half g_cwF[CC * KK]; // conv_w^T fp16 [c][k]
__device__ float g_gpart[NN * KK];
__device__ float g_vp  [(size_t)NSPLIT * NN * KK * CC];  // GEMM2 partials

// ---------------- helpers ----------------------------------------------------
__device__ __forceinline__ uint32_t s2u32(const void* p) {
    uint32_t a;
    asm("{ .reg .u64 t; cvta.to.shared.u64 t, %1; cvt.u32.u64 %0, t; }" : "=r"(a) : "l"(p));
    return a;
}
__device__ __forceinline__ void cpa16(uint32_t d, const void* s) {
    asm volatile("cp.async.cg.shared.global [%0], [%1], 16;" :: "r"(d), "l"(s) : "memory");
}
#define CP_COMMIT() asm volatile("cp.async.commit_group;" ::: "memory")
#define CP_WAIT(n)  asm volatile("cp.async.wait_group %0;" :: "n"(n) : "memory")

#define LDSM4(r0,r1,r2,r3,addr) \
    asm volatile("ldmatrix.sync.aligned.m8n8.x4.shared.b16 {%0,%1,%2,%3}, [%4];" \
                 : "=r"(r0), "=r"(r1), "=r"(r2), "=r"(r3) : "r"(addr))
#define LDSM4T(r0,r1,r2,r3,addr) \
    asm volatile("ldmatrix.sync.aligned.m8n8.x4.trans.shared.b16 {%0,%1,%2,%3}, [%4];" \
                 : "=r"(r0), "=r"(r1), "=r"(r2), "=r"(r3) : "r"(addr))
#define MMAH(d, a, b0, b1) \
    asm volatile("mma.sync.aligned.m16n8k16.row.col.f32.f16.f16.f32 " \
                 "{%0,%1,%2,%3}, {%4,%5,%6,%7}, {%8,%9}, {%0,%1,%2,%3};" \
                 : "+f"((d)[0]), "+f"((d)[1]), "+f"((d)[2]), "+f"((d)[3]) \
                 : "r"((a)[0]), "r"((a)[1]), "r"((a)[2]), "r"((a)[3]), "r"(b0), "r"(b1))

__device__ __forceinline__ uint32_t packh(float a, float b) {
    __half2 h = __floats2half2_rn(a, b);
    return *reinterpret_cast<uint32_t*>(&h);
}

// ---------------- kernel P: transpose + fp16 conv_w -------------------------
__global__ void k_transpose(const float* __restrict__ conv_w) {
    int i = blockIdx.x * 256 + threadIdx.x;   // i = c*64 + k
    if (i < CC * KK) {
        int c = i >> 6, k = i & 63;
        g_cwF[i] = __float2half_rn(conv_w[k * CC + c]);
    }
}

// ---------------- kernel B: GEMM1 fp16 mma (single product) + prep + softmax
// CTA: 128 thr, tile [k=64][p=64], kdim = C = 512 in 32 chunks of 16.
// A = conv_w [c][k] fp16, LDSM4T. B = x chunk fp16, LDSM4T.
struct AsgG {
    float stgX[2][16][68];               // fp32 x stage (cp.async)
    __half awF[2][16][72];               // conv fp16 tiles [c][k] (cp.async)
    __half xsF[16][72];                  // x fp16 tiles [c][p]
};
struct AsgS {
    float S[64][65];                      // raw logits [p][k]
    float ps[4][64];                      // warp wsum partials
    float r1[2][64];                      // ss partials
    float r2[2][64];                      // hs partials
};
union AsgU { AsgG g; AsgS s; };

__global__ __launch_bounds__(128, 8) void k_assign_mma(const float* __restrict__ x,
                                                       const float* __restrict__ aw,
                                                       const float* __restrict__ ab) {
    __shared__ __align__(16) AsgU u;
    __shared__ float saw[CC];
    __shared__ float ivb[64], hmb[64];
    int pt = blockIdx.x, n = blockIdx.y;
    int p0 = pt * 64;
    int tid = threadIdx.x;
    int lane = tid & 31, warp = tid >> 5;

    for (int i = tid; i < CC; i += 128) saw[i] = aw[i];

    // ldmatrix lane addressing
    int lr = lane & 7, lg = lane >> 3;
    int aRow = ((lg & 2) ? 8 : 0) + lr, aCol = (lg & 1) ? 8 : 0;
    int bRow = ((lg & 1) ? 8 : 0) + lr, bCol = warp * 16 + ((lg & 2) ? 8 : 0);
    uint32_t bF = s2u32(&u.g.xsF[bRow][bCol]);
    uint32_t aF[2] = { s2u32(&u.g.awF[0][aRow][aCol]), s2u32(&u.g.awF[1][aRow][aCol]) };

    // staging mapping: thread -> (row cc, 8 cols at seg)
    int cc = tid >> 3, seg = (tid & 7) * 8;
    const float* xsrc = x + ((size_t)(n * CC) + cc) * PP + p0 + seg;

#define AISSUE(ch, b) do {                                                     \
        int _c0 = (ch) * 16;                                                   \
        cpa16(s2u32(&u.g.stgX[b][cc][seg]),     xsrc + (size_t)_c0 * PP);      \
        cpa16(s2u32(&u.g.stgX[b][cc][seg + 4]), xsrc + (size_t)_c0 * PP + 4);  \
        cpa16(s2u32(&u.g.awF[b][cc][seg]), g_cwF + (_c0 + cc) * KK + seg);     \
    } while (0)

    float d[4][2][4] = {};
    float ss = 0.f, hs = 0.f;
    int pcol = tid & 63, rb = (tid >> 6) * 8;

    AISSUE(0, 0); CP_COMMIT();
    for (int ch = 0; ch < 32; ch++) {
        int b = ch & 1;
        if (ch < 31) { AISSUE(ch + 1, b ^ 1); CP_COMMIT(); CP_WAIT(1); }
        else CP_WAIT(0);
        // convert OWN staged x row-segment to fp16 (own data, no sync needed)
        {
            float4 v0 = *reinterpret_cast<float4*>(&u.g.stgX[b][cc][seg]);
            float4 v1 = *reinterpret_cast<float4*>(&u.g.stgX[b][cc][seg + 4]);
            uint4 hv = make_uint4(packh(v0.x, v0.y), packh(v0.z, v0.w),
                                  packh(v1.x, v1.y), packh(v1.z, v1.w));
            *reinterpret_cast<uint4*>(&u.g.xsF[cc][seg]) = hv;
        }
        __syncthreads();
        // prep reductions from fp32 stage (stage live this iter)
#pragma unroll
        for (int r = 0; r < 8; r++) {
            float v = u.g.stgX[b][rb + r][pcol];
            ss += v * v;
            hs += fmaxf(v, 0.f) * saw[ch * 16 + rb + r];
        }
        // B fragments (single fp16)
        uint32_t bf[4];
        LDSM4T(bf[0], bf[1], bf[2], bf[3], bF);
#pragma unroll
        for (int mt = 0; mt < 4; mt++) {
            uint32_t ah[4];
            LDSM4T(ah[0], ah[1], ah[2], ah[3], aF[b] + mt * 32);
            MMAH(d[mt][0], ah, bf[0], bf[1]);
            MMAH(d[mt][1], ah, bf[2], bf[3]);
        }
        __syncthreads();
    }

    // write raw logits S[p][k] from fragments + prep partials
    int grp = lane >> 2, q = lane & 3;
#pragma unroll
    for (int mt = 0; mt < 4; mt++)
#pragma unroll
        for (int ng = 0; ng < 2; ng++) {
            int p = warp * 16 + ng * 8 + q * 2;
            int k = mt * 16 + grp;
            u.s.S[p][k]         = d[mt][ng][0];
            u.s.S[p + 1][k]     = d[mt][ng][1];
            u.s.S[p][k + 8]     = d[mt][ng][2];
            u.s.S[p + 1][k + 8] = d[mt][ng][3];
        }
    u.s.r1[tid >> 6][tid & 63] = ss;
    u.s.r2[tid >> 6][tid & 63] = hs;
    __syncthreads();
    if (tid < 64) {
        float st = u.s.r1[0][tid] + u.s.r1[1][tid];
        float ht = u.s.r2[0][tid] + u.s.r2[1][tid];
        ivb[tid] = 1.f / fmaxf(sqrtf(st), 1e-12f);
        hmb[tid] = fmaxf(ht + ab[0], 0.f);
    }
    __syncthreads();

    // softmax over k per p-row; 4 warps x 16 rows. w2 stored single fp16.
    float pa = 0.f, pb = 0.f;
    for (int r8 = 0; r8 < 16; r8++) {
        int r = warp * 16 + r8;
        float iv = ivb[r];
        float v0 = u.s.S[r][lane] * iv;
        float v1 = u.s.S[r][lane + 32] * iv;
        float m = fmaxf(v0, v1);
#pragma unroll
        for (int o = 16; o > 0; o >>= 1) m = fmaxf(m, __shfl_xor_sync(0xffffffffu, m, o));
        float e0 = __expf(v0 - m), e1 = __expf(v1 - m);
        float s = e0 + e1;
#pragma unroll
        for (int o = 16; o > 0; o >>= 1) s += __shfl_xor_sync(0xffffffffu, s, o);
        float h = hmb[r];
        float sc = h / s;
        float w0 = e0 * sc, w1 = e1 * sc;
        size_t base = ((size_t)n * PP + p0 + r) * KK;
        g_w2f[base + lane]      = __float2half_rn(w0 * iv);
        g_w2f[base + lane + 32] = __float2half_rn(w1 * iv);
        pa += w0; pb += w1;
    }
    u.s.ps[warp][lane]      = pa;
    u.s.ps[warp][lane + 32] = pb;
    __syncthreads();
    if (tid < 64)
        g_wsp[(n * NPT + pt) * KK + tid] =
            u.s.ps[0][tid] + u.s.ps[1][tid] + u.s.ps[2][tid] + u.s.ps[3][tid];
}

// ---------------- kernel C: GEMM2 fp16 mma (single product) -----------------
// CTA: (c-tile 128, n, p-split). D[k=64][c=128] = sum_p w2[k][p] * x[c][p].
// A = w2 fp16 (direct cp.async from g_w2f), B = x fp16.
__global__ __launch_bounds__(128, 4) void k_vlad_mma(const float* __restrict__ x) {
    __shared__ __align__(16) float stgX[2][128][20];      // fp32 x stage
    __shared__ __align__(16) __half xsF[128][24];         // B fp16 tiles [c][p]
    __shared__ __align__(16) __half wsF[2][16][72];       // A^T tiles [p][k]

    int ct = blockIdx.x, n = blockIdx.y, sp = blockIdx.z;
    int c0 = ct * 128;
    int p0  = (sp == 0) ? 0 : 544 + (sp - 1) * 528;
    int nch = (sp == 0) ? 34 : 33;
    int tid = threadIdx.x;
    int lane = tid & 31, warp = tid >> 5;

    int lr = lane & 7, lg = lane >> 3;
    int bRow = warp * 32 + ((lg & 2) ? 8 : 0) + lr;
    int bCol = (lg & 1) ? 8 : 0;
    uint32_t bAF0 = s2u32(&xsF[bRow][bCol]);
    uint32_t bAF1 = s2u32(&xsF[bRow + 16][bCol]);
    int aRow = ((lg & 2) ? 8 : 0) + lr;
    int aColB = (lg & 1) ? 8 : 0;
    uint32_t aAF[2][4];
#pragma unroll
    for (int bb = 0; bb < 2; bb++)
#pragma unroll
        for (int mt = 0; mt < 4; mt++)
            aAF[bb][mt] = s2u32(&wsF[bb][aRow][mt * 16 + aColB]);

    const float* xrow = x + ((size_t)(n * CC + c0 + tid)) * PP + p0;
    int wp = tid >> 3, wk = (tid & 7) * 8;
    size_t wbase = ((size_t)n * PP + p0 + wp) * KK + wk;

#define VISSUE(ci, b) do {                                                     \
        const float* _xp = xrow + (ci) * 16;                                   \
        cpa16(s2u32(&stgX[b][tid][0]),  _xp);                                  \
        cpa16(s2u32(&stgX[b][tid][4]),  _xp + 4);                              \
        cpa16(s2u32(&stgX[b][tid][8]),  _xp + 8);                              \
        cpa16(s2u32(&stgX[b][tid][12]), _xp + 12);                             \
        cpa16(s2u32(&wsF[b][wp][wk]), g_w2f + wbase + (size_t)(ci) * 16 * KK); \
    } while (0)

    float d[4][4][4] = {};

    VISSUE(0, 0); CP_COMMIT();
    for (int i = 0; i < nch; i++) {
        int b = i & 1;
        if (i + 1 < nch) { VISSUE(i + 1, b ^ 1); CP_COMMIT(); CP_WAIT(1); }
        else CP_WAIT(0);
        // convert OWN staged x (16 values) to single fp16
        {
            uint32_t hp[8];
#pragma unroll
            for (int q = 0; q < 4; q++) {
                float4 v = *reinterpret_cast<float4*>(&stgX[b][tid][q * 4]);
                hp[q * 2]     = packh(v.x, v.y);
                hp[q * 2 + 1] = packh(v.z, v.w);
            }
            *reinterpret_cast<uint4*>(&xsF[tid][0]) = make_uint4(hp[0], hp[1], hp[2], hp[3]);
            *reinterpret_cast<uint4*>(&xsF[tid][8]) = make_uint4(hp[4], hp[5], hp[6], hp[7]);
        }
        __syncthreads();
        uint32_t bf[8];
        LDSM4(bf[0], bf[1], bf[2], bf[3], bAF0);
        LDSM4(bf[4], bf[5], bf[6], bf[7], bAF1);
#pragma unroll
        for (int mt = 0; mt < 4; mt++) {
            uint32_t af[4];
            LDSM4T(af[0], af[1], af[2], af[3], aAF[b][mt]);
#pragma unroll
            for (int ng = 0; ng < 4; ng++)
                MMAH(d[mt][ng], af, bf[ng * 2], bf[ng * 2 + 1]);
        }
        __syncthreads();
    }
    int grp = lane >> 2, q = lane & 3;
#pragma unroll
    for (int mt = 0; mt < 4; mt++)
#pragma unroll
        for (int ng = 0; ng < 4; ng++) {
            int k = mt * 16 + grp;
            int c = c0 + warp * 32 + ng * 8 + q * 2;
            size_t o = (((size_t)sp * NN + n) * KK + k) * CC + c;
            *reinterpret_cast<float2*>(&g_vp[o]) =
                make_float2(d[mt][ng][0], d[mt][ng][1]);
            *reinterpret_cast<float2*>(&g_vp[o + 8 * CC]) =
                make_float2(d[mt][ng][2], d[mt][ng][3]);
        }
}

// ---------------- kernel E: reduce partials + residual + intra L2 ----------
// Warp-shuffle reduction (2 syncs instead of 8).
__global__ __launch_bounds__(256) void k_norm1(const float* __restrict__ cent,
                                               float* __restrict__ out) {
    __shared__ float red[8];
    __shared__ float stot;
    int k = blockIdx.x, n = blockIdx.y, tid = threadIdx.x;
    int lane = tid & 31, wrp = tid >> 5;
    float wsum = 0.f;
#pragma unroll
    for (int t = 0; t < NPT; t++) wsum += g_wsp[(n * NPT + t) * KK + k];

    float t1a = 0.f, t1b = 0.f;
#pragma unroll
    for (int s = 0; s < NSPLIT; s++) {
        size_t b = (((size_t)s * NN + n) * KK + k) * CC;
        t1a += g_vp[b + tid];
        t1b += g_vp[b + tid + 256];
    }
    size_t base = (size_t)n * KC + (size_t)k * CC;
    float v1 = t1a - wsum * cent[k * CC + tid];
    float v2 = t1b - wsum * cent[k * CC + tid + 256];
    float v = v1 * v1 + v2 * v2;
#pragma unroll
    for (int o = 16; o > 0; o >>= 1) v += __shfl_xor_sync(0xffffffffu, v, o);
    if (lane == 0) red[wrp] = v;
    __syncthreads();
    if (tid == 0) {
        float t = red[0] + red[1] + red[2] + red[3]
                + red[4] + red[5] + red[6] + red[7];
        stot = t;
        g_gpart[n * KK + k] = 1.f;   // placeholder; fixed below with exact value
    }
    __syncthreads();
    float tot = stot;
    float inv = 1.f / fmaxf(sqrtf(tot), 1e-12f);
    out[base + tid]       = v1 * inv;
    out[base + tid + 256] = v2 * inv;
    if (tid == 0) g_gpart[n * KK + k] = tot * inv * inv;
}

// ---------------- kernel F: global L2 normalize (float4) --------------------
__global__ __launch_bounds__(256) void k_norm2(float* __restrict__ out) {
    __shared__ float ginv;
    size_t i4 = ((size_t)blockIdx.x * 256 + threadIdx.x) * 4;
    int n = (int)(i4 >> 15);                   // 32768 elements per n
    int lane = threadIdx.x & 31;
    if (threadIdx.x < 32) {
        float t = g_gpart[n * KK + lane] + g_gpart[n * KK + lane + 32];
#pragma unroll
        for (int o = 16; o > 0; o >>= 1) t += __shfl_xor_sync(0xffffffffu, t, o);
        if (lane == 0) ginv = 1.f / fmaxf(sqrtf(t), 1e-12f);
    }
    __syncthreads();
    float g = ginv;
    float4 v = *reinterpret_cast<float4*>(out + i4);
    v.x *= g; v.y *= g; v.z *= g; v.w *= g;
    *reinterpret_cast<float4*>(out + i4) = v;
}

// ---------------- launch -----------------------------------------------------
extern "C" void kernel_launch(void* const* d_in, const int* in_sizes, int n_in,
                              void* d_out, int out_size) {
    const float* x      = (const float*)d_in[0];
    const float* conv_w = (const float*)d_in[1];
    const float* attn_w = (const float*)d_in[2];
    const float* attn_b = (const float*)d_in[3];
    const float* cent   = (const float*)d_in[4];
    float* out = (float*)d_out;
    (void)in_sizes; (void)n_in; (void)out_size;

    k_transpose<<<(CC * KK + 255) / 256, 256>>>(conv_w);
    k_assign_mma<<<dim3(NPT, NN), 128>>>(x, attn_w, attn_b);
    k_vlad_mma<<<dim3(4, NN, NSPLIT), 128>>>(x);
    k_norm1<<<dim3(KK, NN), 256>>>(cent, out);
    k_norm2<<<(NN * KC) / 1024, 256>>>(out);
}

// round 15
// speedup vs baseline: 1.5434x; 1.0867x over previous
#include <cuda_runtime.h>
#include <cuda_fp16.h>
#include <math.h>
#include <stdint.h>

// Problem constants
#define NN 48
#define CC 512
#define PP 1600      // 40*40
#define KK 64
#define KC 32768     // K*C
#define NPT 25       // P / 64 tiles (k_assign)
#define NSPLIT 3     // split-P factor for GEMM2

// ---------------- scratch ---------------------------------------------------
__device__ __align__(256) __half g_w2f[(size_t)NN * PP * KK];  // w2 fp16 [n][p][k]
__device__ __align__(256) __half g_xh [(size_t)NN * CC * PP];  // x fp16 [n][c][p]
__device__ float g_wsp [NN * NPT * KK];          // partial wsum [n][pt][k]
__device__ __align__(256) __half g_cwF[CC * KK]; // conv_w^T fp16 [c][k]
__device__ float g_gpart[NN * KK];
__device__ float g_vp  [(size_t)NSPLIT * NN * KK * CC];  // GEMM2 partials

// ---------------- helpers ----------------------------------------------------
__device__ __forceinline__ uint32_t s2u32(const void* p) {
    uint32_t a;
    asm("{ .reg .u64 t; cvta.to.shared.u64 t, %1; cvt.u32.u64 %0, t; }" : "=r"(a) : "l"(p));
    return a;
}
__device__ __forceinline__ void cpa16(uint32_t d, const void* s) {
    asm volatile("cp.async.cg.shared.global [%0], [%1], 16;" :: "r"(d), "l"(s) : "memory");
}
#define CP_COMMIT() asm volatile("cp.async.commit_group;" ::: "memory")
#define CP_WAIT(n)  asm volatile("cp.async.wait_group %0;" :: "n"(n) : "memory")

#define LDSM4(r0,r1,r2,r3,addr) \
    asm volatile("ldmatrix.sync.aligned.m8n8.x4.shared.b16 {%0,%1,%2,%3}, [%4];" \
                 : "=r"(r0), "=r"(r1), "=r"(r2), "=r"(r3) : "r"(addr))
#define LDSM4T(r0,r1,r2,r3,addr) \
    asm volatile("ldmatrix.sync.aligned.m8n8.x4.trans.shared.b16 {%0,%1,%2,%3}, [%4];" \
                 : "=r"(r0), "=r"(r1), "=r"(r2), "=r"(r3) : "r"(addr))
#define MMAH(d, a, b0, b1) \
    asm volatile("mma.sync.aligned.m16n8k16.row.col.f32.f16.f16.f32 " \
                 "{%0,%1,%2,%3}, {%4,%5,%6,%7}, {%8,%9}, {%0,%1,%2,%3};" \
                 : "+f"((d)[0]), "+f"((d)[1]), "+f"((d)[2]), "+f"((d)[3]) \
                 : "r"((a)[0]), "r"((a)[1]), "r"((a)[2]), "r"((a)[3]), "r"(b0), "r"(b1))

__device__ __forceinline__ uint32_t packh(float a, float b) {
    __half2 h = __floats2half2_rn(a, b);
    return *reinterpret_cast<uint32_t*>(&h);
}

// ---------------- kernel P: transpose + fp16 conv_w -------------------------
__global__ void k_transpose(const float* __restrict__ conv_w) {
    int i = blockIdx.x * 256 + threadIdx.x;   // i = c*64 + k
    if (i < CC * KK) {
        int c = i >> 6, k = i & 63;
        g_cwF[i] = __float2half_rn(conv_w[k * CC + c]);
    }
}

// ---------------- kernel B: GEMM1 fp16 mma + prep + softmax + x-fp16 export -
// CTA: 128 thr, tile [k=64][p=64], kdim = C = 512 in 32 chunks of 16.
// A = conv_w [c][k] fp16, LDSM4T. B = x chunk fp16, LDSM4T.
// The fp16-converted x tiles are also stored to g_xh for k_vlad to reuse.
struct AsgG {
    float stgX[2][16][68];               // fp32 x stage (cp.async)
    __half awF[2][16][72];               // conv fp16 tiles [c][k] (cp.async)
    __half xsF[16][72];                  // x fp16 tiles [c][p]
};
struct AsgS {
    float S[64][65];                      // raw logits [p][k]
    float ps[4][64];                      // warp wsum partials
    float r1[2][64];                      // ss partials
    float r2[2][64];                      // hs partials
};
union AsgU { AsgG g; AsgS s; };

__global__ __launch_bounds__(128, 8) void k_assign_mma(const float* __restrict__ x,
                                                       const float* __restrict__ aw,
                                                       const float* __restrict__ ab) {
    __shared__ __align__(16) AsgU u;
    __shared__ float saw[CC];
    __shared__ float ivb[64], hmb[64];
    int pt = blockIdx.x, n = blockIdx.y;
    int p0 = pt * 64;
    int tid = threadIdx.x;
    int lane = tid & 31, warp = tid >> 5;

    for (int i = tid; i < CC; i += 128) saw[i] = aw[i];

    // ldmatrix lane addressing
    int lr = lane & 7, lg = lane >> 3;
    int aRow = ((lg & 2) ? 8 : 0) + lr, aCol = (lg & 1) ? 8 : 0;
    int bRow = ((lg & 1) ? 8 : 0) + lr, bCol = warp * 16 + ((lg & 2) ? 8 : 0);
    uint32_t bF = s2u32(&u.g.xsF[bRow][bCol]);
    uint32_t aF[2] = { s2u32(&u.g.awF[0][aRow][aCol]), s2u32(&u.g.awF[1][aRow][aCol]) };

    // staging mapping: thread -> (row cc, 8 cols at seg)
    int cc = tid >> 3, seg = (tid & 7) * 8;
    const float* xsrc = x + ((size_t)(n * CC) + cc) * PP + p0 + seg;
    __half* xdst = g_xh + ((size_t)(n * CC) + cc) * PP + p0 + seg;

#define AISSUE(ch, b) do {                                                     \
        int _c0 = (ch) * 16;                                                   \
        cpa16(s2u32(&u.g.stgX[b][cc][seg]),     xsrc + (size_t)_c0 * PP);      \
        cpa16(s2u32(&u.g.stgX[b][cc][seg + 4]), xsrc + (size_t)_c0 * PP + 4);  \
        cpa16(s2u32(&u.g.awF[b][cc][seg]), g_cwF + (_c0 + cc) * KK + seg);     \
    } while (0)

    float d[4][2][4] = {};
    float ss = 0.f, hs = 0.f;
    int pcol = tid & 63, rb = (tid >> 6) * 8;

    AISSUE(0, 0); CP_COMMIT();
    for (int ch = 0; ch < 32; ch++) {
        int b = ch & 1;
        if (ch < 31) { AISSUE(ch + 1, b ^ 1); CP_COMMIT(); CP_WAIT(1); }
        else CP_WAIT(0);
        // convert OWN staged x row-segment to fp16; store to smem AND g_xh
        {
            float4 v0 = *reinterpret_cast<float4*>(&u.g.stgX[b][cc][seg]);
            float4 v1 = *reinterpret_cast<float4*>(&u.g.stgX[b][cc][seg + 4]);
            uint4 hv = make_uint4(packh(v0.x, v0.y), packh(v0.z, v0.w),
                                  packh(v1.x, v1.y), packh(v1.z, v1.w));
            *reinterpret_cast<uint4*>(&u.g.xsF[cc][seg]) = hv;
            *reinterpret_cast<uint4*>(xdst) = hv;
            xdst += (size_t)16 * PP;
        }
        __syncthreads();
        // prep reductions from fp32 stage (stage live this iter)
#pragma unroll
        for (int r = 0; r < 8; r++) {
            float v = u.g.stgX[b][rb + r][pcol];
            ss += v * v;
            hs += fmaxf(v, 0.f) * saw[ch * 16 + rb + r];
        }
        // B fragments (single fp16)
        uint32_t bf[4];
        LDSM4T(bf[0], bf[1], bf[2], bf[3], bF);
#pragma unroll
        for (int mt = 0; mt < 4; mt++) {
            uint32_t ah[4];
            LDSM4T(ah[0], ah[1], ah[2], ah[3], aF[b] + mt * 32);
            MMAH(d[mt][0], ah, bf[0], bf[1]);
            MMAH(d[mt][1], ah, bf[2], bf[3]);
        }
        __syncthreads();
    }

    // write raw logits S[p][k] from fragments + prep partials
    int grp = lane >> 2, q = lane & 3;
#pragma unroll
    for (int mt = 0; mt < 4; mt++)
#pragma unroll
        for (int ng = 0; ng < 2; ng++) {
            int p = warp * 16 + ng * 8 + q * 2;
            int k = mt * 16 + grp;
            u.s.S[p][k]         = d[mt][ng][0];
            u.s.S[p + 1][k]     = d[mt][ng][1];
            u.s.S[p][k + 8]     = d[mt][ng][2];
            u.s.S[p + 1][k + 8] = d[mt][ng][3];
        }
    u.s.r1[tid >> 6][tid & 63] = ss;
    u.s.r2[tid >> 6][tid & 63] = hs;
    __syncthreads();
    if (tid < 64) {
        float st = u.s.r1[0][tid] + u.s.r1[1][tid];
        float ht = u.s.r2[0][tid] + u.s.r2[1][tid];
        ivb[tid] = 1.f / fmaxf(sqrtf(st), 1e-12f);
        hmb[tid] = fmaxf(ht + ab[0], 0.f);
    }
    __syncthreads();

    // softmax over k per p-row; 4 warps x 16 rows. w2 stored single fp16.
    float pa = 0.f, pb = 0.f;
    for (int r8 = 0; r8 < 16; r8++) {
        int r = warp * 16 + r8;
        float iv = ivb[r];
        float v0 = u.s.S[r][lane] * iv;
        float v1 = u.s.S[r][lane + 32] * iv;
        float m = fmaxf(v0, v1);
#pragma unroll
        for (int o = 16; o > 0; o >>= 1) m = fmaxf(m, __shfl_xor_sync(0xffffffffu, m, o));
        float e0 = __expf(v0 - m), e1 = __expf(v1 - m);
        float s = e0 + e1;
#pragma unroll
        for (int o = 16; o > 0; o >>= 1) s += __shfl_xor_sync(0xffffffffu, s, o);
        float h = hmb[r];
        float sc = h / s;
        float w0 = e0 * sc, w1 = e1 * sc;
        size_t base = ((size_t)n * PP + p0 + r) * KK;
        g_w2f[base + lane]      = __float2half_rn(w0 * iv);
        g_w2f[base + lane + 32] = __float2half_rn(w1 * iv);
        pa += w0; pb += w1;
    }
    u.s.ps[warp][lane]      = pa;
    u.s.ps[warp][lane + 32] = pb;
    __syncthreads();
    if (tid < 64)
        g_wsp[(n * NPT + pt) * KK + tid] =
            u.s.ps[0][tid] + u.s.ps[1][tid] + u.s.ps[2][tid] + u.s.ps[3][tid];
}

// ---------------- kernel C: GEMM2 fp16 mma, fp16 x via g_xh -----------------
// CTA: (c-tile 128, n, p-split). D[k=64][c=128] = sum_p w2[k][p] * x[c][p].
// A = w2 fp16, B = x fp16 — BOTH direct cp.async into ldmatrix tiles.
__global__ __launch_bounds__(128, 4) void k_vlad_mma(const float* __restrict__ x) {
    __shared__ __align__(16) __half xsF[2][128][24];      // B fp16 tiles [c][p]
    __shared__ __align__(16) __half wsF[2][16][72];       // A^T tiles [p][k]

    int ct = blockIdx.x, n = blockIdx.y, sp = blockIdx.z;
    int c0 = ct * 128;
    int p0  = (sp == 0) ? 0 : 544 + (sp - 1) * 528;
    int nch = (sp == 0) ? 34 : 33;
    int tid = threadIdx.x;
    int lane = tid & 31, warp = tid >> 5;
    (void)x;

    int lr = lane & 7, lg = lane >> 3;
    int bRow = warp * 32 + ((lg & 2) ? 8 : 0) + lr;
    int bCol = (lg & 1) ? 8 : 0;
    uint32_t bAF0[2] = { s2u32(&xsF[0][bRow][bCol]),      s2u32(&xsF[1][bRow][bCol]) };
    uint32_t bAF1[2] = { s2u32(&xsF[0][bRow + 16][bCol]), s2u32(&xsF[1][bRow + 16][bCol]) };
    int aRow = ((lg & 2) ? 8 : 0) + lr;
    int aColB = (lg & 1) ? 8 : 0;
    uint32_t aAF[2][4];
#pragma unroll
    for (int bb = 0; bb < 2; bb++)
#pragma unroll
        for (int mt = 0; mt < 4; mt++)
            aAF[bb][mt] = s2u32(&wsF[bb][aRow][mt * 16 + aColB]);

    const __half* xrow = g_xh + ((size_t)(n * CC + c0 + tid)) * PP + p0;
    int wp = tid >> 3, wk = (tid & 7) * 8;
    size_t wbase = ((size_t)n * PP + p0 + wp) * KK + wk;

#define VISSUE(ci, b) do {                                                     \
        const __half* _xp = xrow + (ci) * 16;                                  \
        cpa16(s2u32(&xsF[b][tid][0]), _xp);                                    \
        cpa16(s2u32(&xsF[b][tid][8]), _xp + 8);                                \
        cpa16(s2u32(&wsF[b][wp][wk]), g_w2f + wbase + (size_t)(ci) * 16 * KK); \
    } while (0)

    float d[4][4][4] = {};

    VISSUE(0, 0); CP_COMMIT();
    for (int i = 0; i < nch; i++) {
        int b = i & 1;
        if (i + 1 < nch) { VISSUE(i + 1, b ^ 1); CP_COMMIT(); CP_WAIT(1); }
        else CP_WAIT(0);
        __syncthreads();
        uint32_t bf[8];
        LDSM4(bf[0], bf[1], bf[2], bf[3], bAF0[b]);
        LDSM4(bf[4], bf[5], bf[6], bf[7], bAF1[b]);
#pragma unroll
        for (int mt = 0; mt < 4; mt++) {
            uint32_t af[4];
            LDSM4T(af[0], af[1], af[2], af[3], aAF[b][mt]);
#pragma unroll
            for (int ng = 0; ng < 4; ng++)
                MMAH(d[mt][ng], af, bf[ng * 2], bf[ng * 2 + 1]);
        }
        __syncthreads();
    }
    int grp = lane >> 2, q = lane & 3;
#pragma unroll
    for (int mt = 0; mt < 4; mt++)
#pragma unroll
        for (int ng = 0; ng < 4; ng++) {
            int k = mt * 16 + grp;
            int c = c0 + warp * 32 + ng * 8 + q * 2;
            size_t o = (((size_t)sp * NN + n) * KK + k) * CC + c;
            *reinterpret_cast<float2*>(&g_vp[o]) =
                make_float2(d[mt][ng][0], d[mt][ng][1]);
            *reinterpret_cast<float2*>(&g_vp[o + 8 * CC]) =
                make_float2(d[mt][ng][2], d[mt][ng][3]);
        }
}

// ---------------- kernel E: reduce partials + residual + intra L2 ----------
__global__ __launch_bounds__(256) void k_norm1(const float* __restrict__ cent,
                                               float* __restrict__ out) {
    __shared__ float red[8];
    __shared__ float stot;
    int k = blockIdx.x, n = blockIdx.y, tid = threadIdx.x;
    int lane = tid & 31, wrp = tid >> 5;
    float wsum = 0.f;
#pragma unroll
    for (int t = 0; t < NPT; t++) wsum += g_wsp[(n * NPT + t) * KK + k];

    float t1a = 0.f, t1b = 0.f;
#pragma unroll
    for (int s = 0; s < NSPLIT; s++) {
        size_t b = (((size_t)s * NN + n) * KK + k) * CC;
        t1a += g_vp[b + tid];
        t1b += g_vp[b + tid + 256];
    }
    size_t base = (size_t)n * KC + (size_t)k * CC;
    float v1 = t1a - wsum * cent[k * CC + tid];
    float v2 = t1b - wsum * cent[k * CC + tid + 256];
    float v = v1 * v1 + v2 * v2;
#pragma unroll
    for (int o = 16; o > 0; o >>= 1) v += __shfl_xor_sync(0xffffffffu, v, o);
    if (lane == 0) red[wrp] = v;
    __syncthreads();
    if (tid == 0) {
        stot = red[0] + red[1] + red[2] + red[3]
             + red[4] + red[5] + red[6] + red[7];
    }
    __syncthreads();
    float tot = stot;
    float inv = 1.f / fmaxf(sqrtf(tot), 1e-12f);
    out[base + tid]       = v1 * inv;
    out[base + tid + 256] = v2 * inv;
    if (tid == 0) g_gpart[n * KK + k] = tot * inv * inv;
}

// ---------------- kernel F: global L2 normalize (float4) --------------------
__global__ __launch_bounds__(256) void k_norm2(float* __restrict__ out) {
    __shared__ float ginv;
    size_t i4 = ((size_t)blockIdx.x * 256 + threadIdx.x) * 4;
    int n = (int)(i4 >> 15);                   // 32768 elements per n
    int lane = threadIdx.x & 31;
    if (threadIdx.x < 32) {
        float t = g_gpart[n * KK + lane] + g_gpart[n * KK + lane + 32];
#pragma unroll
        for (int o = 16; o > 0; o >>= 1) t += __shfl_xor_sync(0xffffffffu, t, o);
        if (lane == 0) ginv = 1.f / fmaxf(sqrtf(t), 1e-12f);
    }
    __syncthreads();
    float g = ginv;
    float4 v = *reinterpret_cast<float4*>(out + i4);
    v.x *= g; v.y *= g; v.z *= g; v.w *= g;
    *reinterpret_cast<float4*>(out + i4) = v;
}

// ---------------- launch -----------------------------------------------------
extern "C" void kernel_launch(void* const* d_in, const int* in_sizes, int n_in,
                              void* d_out, int out_size) {
    const float* x      = (const float*)d_in[0];
    const float* conv_w = (const float*)d_in[1];
    const float* attn_w = (const float*)d_in[2];
    const float* attn_b = (const float*)d_in[3];
    const float* cent   = (const float*)d_in[4];
    float* out = (float*)d_out;
    (void)in_sizes; (void)n_in; (void)out_size;

    k_transpose<<<(CC * KK + 255) / 256, 256>>>(conv_w);
    k_assign_mma<<<dim3(NPT, NN), 128>>>(x, attn_w, attn_b);
    k_vlad_mma<<<dim3(4, NN, NSPLIT), 128>>>(x);
    k_norm1<<<dim3(KK, NN), 256>>>(cent, out);
    k_norm2<<<(NN * KC) / 1024, 256>>>(out);
}

// round 16
// speedup vs baseline: 1.5654x; 1.0143x over previous
#include <cuda_runtime.h>
#include <cuda_fp16.h>
#include <math.h>
#include <stdint.h>

// Problem constants
#define NN 48
#define CC 512
#define PP 1600      // 40*40
#define KK 64
#define KC 32768     // K*C
#define NPT 25       // P / 64 tiles (k_assign)
#define NSPLIT 3     // split-P factor for GEMM2

// ---------------- scratch ---------------------------------------------------
__device__ __align__(256) __half g_w2f[(size_t)NN * PP * KK];  // w2 fp16 [n][p][k]
__device__ __align__(256) __half g_xh [(size_t)NN * CC * PP];  // x fp16 [n][c][p]
__device__ float g_wsp [NN * NPT * KK];          // partial wsum [n][pt][k]
__device__ __align__(256) __half g_cwF[CC * KK]; // conv_w^T fp16 [c][k]
__device__ float g_gpart[NN * KK];
__device__ float g_vp  [(size_t)NSPLIT * NN * KK * CC];  // GEMM2 partials

// ---------------- helpers ----------------------------------------------------
__device__ __forceinline__ uint32_t s2u32(const void* p) {
    uint32_t a;
    asm("{ .reg .u64 t; cvta.to.shared.u64 t, %1; cvt.u32.u64 %0, t; }" : "=r"(a) : "l"(p));
    return a;
}
__device__ __forceinline__ void cpa16(uint32_t d, const void* s) {
    asm volatile("cp.async.cg.shared.global [%0], [%1], 16;" :: "r"(d), "l"(s) : "memory");
}
#define CP_COMMIT() asm volatile("cp.async.commit_group;" ::: "memory")
#define CP_WAIT(n)  asm volatile("cp.async.wait_group %0;" :: "n"(n) : "memory")

#define LDSM4(r0,r1,r2,r3,addr) \
    asm volatile("ldmatrix.sync.aligned.m8n8.x4.shared.b16 {%0,%1,%2,%3}, [%4];" \
                 : "=r"(r0), "=r"(r1), "=r"(r2), "=r"(r3) : "r"(addr))
#define LDSM4T(r0,r1,r2,r3,addr) \
    asm volatile("ldmatrix.sync.aligned.m8n8.x4.trans.shared.b16 {%0,%1,%2,%3}, [%4];" \
                 : "=r"(r0), "=r"(r1), "=r"(r2), "=r"(r3) : "r"(addr))
#define MMAH(d, a, b0, b1) \
    asm volatile("mma.sync.aligned.m16n8k16.row.col.f32.f16.f16.f32 " \
                 "{%0,%1,%2,%3}, {%4,%5,%6,%7}, {%8,%9}, {%0,%1,%2,%3};" \
                 : "+f"((d)[0]), "+f"((d)[1]), "+f"((d)[2]), "+f"((d)[3]) \
                 : "r"((a)[0]), "r"((a)[1]), "r"((a)[2]), "r"((a)[3]), "r"(b0), "r"(b1))

__device__ __forceinline__ uint32_t packh(float a, float b) {
    __half2 h = __floats2half2_rn(a, b);
    return *reinterpret_cast<uint32_t*>(&h);
}

// ---------------- kernel P: transpose + fp16 conv_w -------------------------
__global__ void k_transpose(const float* __restrict__ conv_w) {
    int i = blockIdx.x * 256 + threadIdx.x;   // i = c*64 + k
    if (i < CC * KK) {
        int c = i >> 6, k = i & 63;
        g_cwF[i] = __float2half_rn(conv_w[k * CC + c]);
    }
}

// ---------------- kernel B: GEMM1 fp16 mma + prep + softmax + x-fp16 export -
// CTA: 128 thr, tile [k=64][p=64], kdim = C = 512 in 32 chunks of 16.
// Depth-3 cp.async pipeline (issue-ahead-2).
struct AsgG {
    float stgX[3][16][68];               // fp32 x stage (cp.async ring)
    __half awF[3][16][72];               // conv fp16 tiles [c][k] (cp.async ring)
    __half xsF[16][72];                  // x fp16 tiles [c][p]
};
struct AsgS {
    float S[64][65];                      // raw logits [p][k]
    float ps[4][64];                      // warp wsum partials
    float r1[2][64];                      // ss partials
    float r2[2][64];                      // hs partials
};
union AsgU { AsgG g; AsgS s; };

__global__ __launch_bounds__(128, 8) void k_assign_mma(const float* __restrict__ x,
                                                       const float* __restrict__ aw,
                                                       const float* __restrict__ ab) {
    __shared__ __align__(16) AsgU u;
    __shared__ float saw[CC];
    __shared__ float ivb[64], hmb[64];
    int pt = blockIdx.x, n = blockIdx.y;
    int p0 = pt * 64;
    int tid = threadIdx.x;
    int lane = tid & 31, warp = tid >> 5;

    for (int i = tid; i < CC; i += 128) saw[i] = aw[i];

    // ldmatrix lane addressing
    int lr = lane & 7, lg = lane >> 3;
    int aRow = ((lg & 2) ? 8 : 0) + lr, aCol = (lg & 1) ? 8 : 0;
    int bRow = ((lg & 1) ? 8 : 0) + lr, bCol = warp * 16 + ((lg & 2) ? 8 : 0);
    uint32_t bF = s2u32(&u.g.xsF[bRow][bCol]);
    uint32_t aF[3] = { s2u32(&u.g.awF[0][aRow][aCol]),
                       s2u32(&u.g.awF[1][aRow][aCol]),
                       s2u32(&u.g.awF[2][aRow][aCol]) };

    // staging mapping: thread -> (row cc, 8 cols at seg)
    int cc = tid >> 3, seg = (tid & 7) * 8;
    const float* xsrc = x + ((size_t)(n * CC) + cc) * PP + p0 + seg;
    __half* xdst = g_xh + ((size_t)(n * CC) + cc) * PP + p0 + seg;

#define AISSUE(ch, b) do {                                                     \
        int _c0 = (ch) * 16;                                                   \
        cpa16(s2u32(&u.g.stgX[b][cc][seg]),     xsrc + (size_t)_c0 * PP);      \
        cpa16(s2u32(&u.g.stgX[b][cc][seg + 4]), xsrc + (size_t)_c0 * PP + 4);  \
        cpa16(s2u32(&u.g.awF[b][cc][seg]), g_cwF + (_c0 + cc) * KK + seg);     \
    } while (0)

    float d[4][2][4] = {};
    float ss = 0.f, hs = 0.f;
    int pcol = tid & 63, rb = (tid >> 6) * 8;

    AISSUE(0, 0); CP_COMMIT();
    AISSUE(1, 1); CP_COMMIT();
    for (int ch = 0; ch < 32; ch++) {
        int b = ch % 3;
        if (ch + 2 < 32) { AISSUE(ch + 2, (ch + 2) % 3); CP_COMMIT(); }
        if (ch < 30) CP_WAIT(2);
        else if (ch == 30) CP_WAIT(1);
        else CP_WAIT(0);
        // convert OWN staged x row-segment to fp16; store to smem AND g_xh
        {
            float4 v0 = *reinterpret_cast<float4*>(&u.g.stgX[b][cc][seg]);
            float4 v1 = *reinterpret_cast<float4*>(&u.g.stgX[b][cc][seg + 4]);
            uint4 hv = make_uint4(packh(v0.x, v0.y), packh(v0.z, v0.w),
                                  packh(v1.x, v1.y), packh(v1.z, v1.w));
            *reinterpret_cast<uint4*>(&u.g.xsF[cc][seg]) = hv;
            *reinterpret_cast<uint4*>(xdst) = hv;
            xdst += (size_t)16 * PP;
        }
        __syncthreads();
        // prep reductions from fp32 stage (stage live this iter)
#pragma unroll
        for (int r = 0; r < 8; r++) {
            float v = u.g.stgX[b][rb + r][pcol];
            ss += v * v;
            hs += fmaxf(v, 0.f) * saw[ch * 16 + rb + r];
        }
        // B fragments (single fp16)
        uint32_t bf[4];
        LDSM4T(bf[0], bf[1], bf[2], bf[3], bF);
#pragma unroll
        for (int mt = 0; mt < 4; mt++) {
            uint32_t ah[4];
            LDSM4T(ah[0], ah[1], ah[2], ah[3], aF[b] + mt * 32);
            MMAH(d[mt][0], ah, bf[0], bf[1]);
            MMAH(d[mt][1], ah, bf[2], bf[3]);
        }
        __syncthreads();
    }

    // write raw logits S[p][k] from fragments + prep partials
    int grp = lane >> 2, q = lane & 3;
#pragma unroll
    for (int mt = 0; mt < 4; mt++)
#pragma unroll
        for (int ng = 0; ng < 2; ng++) {
            int p = warp * 16 + ng * 8 + q * 2;
            int k = mt * 16 + grp;
            u.s.S[p][k]         = d[mt][ng][0];
            u.s.S[p + 1][k]     = d[mt][ng][1];
            u.s.S[p][k + 8]     = d[mt][ng][2];
            u.s.S[p + 1][k + 8] = d[mt][ng][3];
        }
    u.s.r1[tid >> 6][tid & 63] = ss;
    u.s.r2[tid >> 6][tid & 63] = hs;
    __syncthreads();
    if (tid < 64) {
        float st = u.s.r1[0][tid] + u.s.r1[1][tid];
        float ht = u.s.r2[0][tid] + u.s.r2[1][tid];
        ivb[tid] = 1.f / fmaxf(sqrtf(st), 1e-12f);
        hmb[tid] = fmaxf(ht + ab[0], 0.f);
    }
    __syncthreads();

    // softmax over k per p-row; 4 warps x 16 rows. w2 stored single fp16.
    float pa = 0.f, pb = 0.f;
    for (int r8 = 0; r8 < 16; r8++) {
        int r = warp * 16 + r8;
        float iv = ivb[r];
        float v0 = u.s.S[r][lane] * iv;
        float v1 = u.s.S[r][lane + 32] * iv;
        float m = fmaxf(v0, v1);
#pragma unroll
        for (int o = 16; o > 0; o >>= 1) m = fmaxf(m, __shfl_xor_sync(0xffffffffu, m, o));
        float e0 = __expf(v0 - m), e1 = __expf(v1 - m);
        float s = e0 + e1;
#pragma unroll
        for (int o = 16; o > 0; o >>= 1) s += __shfl_xor_sync(0xffffffffu, s, o);
        float h = hmb[r];
        float sc = h / s;
        float w0 = e0 * sc, w1 = e1 * sc;
        size_t base = ((size_t)n * PP + p0 + r) * KK;
        g_w2f[base + lane]      = __float2half_rn(w0 * iv);
        g_w2f[base + lane + 32] = __float2half_rn(w1 * iv);
        pa += w0; pb += w1;
    }
    u.s.ps[warp][lane]      = pa;
    u.s.ps[warp][lane + 32] = pb;
    __syncthreads();
    if (tid < 64)
        g_wsp[(n * NPT + pt) * KK + tid] =
            u.s.ps[0][tid] + u.s.ps[1][tid] + u.s.ps[2][tid] + u.s.ps[3][tid];
}

// ---------------- kernel C: GEMM2 fp16 mma, fp16 x via g_xh -----------------
// CTA: (c-tile 128, n, p-split). D[k=64][c=128] = sum_p w2[k][p] * x[c][p].
// Depth-3 cp.async pipeline (issue-ahead-2).
__global__ __launch_bounds__(128, 4) void k_vlad_mma(const float* __restrict__ x) {
    __shared__ __align__(16) __half xsF[3][128][24];      // B fp16 tiles [c][p]
    __shared__ __align__(16) __half wsF[3][16][72];       // A^T tiles [p][k]

    int ct = blockIdx.x, n = blockIdx.y, sp = blockIdx.z;
    int c0 = ct * 128;
    int p0  = (sp == 0) ? 0 : 544 + (sp - 1) * 528;
    int nch = (sp == 0) ? 34 : 33;
    int tid = threadIdx.x;
    int lane = tid & 31, warp = tid >> 5;
    (void)x;

    int lr = lane & 7, lg = lane >> 3;
    int bRow = warp * 32 + ((lg & 2) ? 8 : 0) + lr;
    int bCol = (lg & 1) ? 8 : 0;
    uint32_t bAF0[3], bAF1[3];
    int aRow = ((lg & 2) ? 8 : 0) + lr;
    int aColB = (lg & 1) ? 8 : 0;
    uint32_t aAF[3][4];
#pragma unroll
    for (int bb = 0; bb < 3; bb++) {
        bAF0[bb] = s2u32(&xsF[bb][bRow][bCol]);
        bAF1[bb] = s2u32(&xsF[bb][bRow + 16][bCol]);
#pragma unroll
        for (int mt = 0; mt < 4; mt++)
            aAF[bb][mt] = s2u32(&wsF[bb][aRow][mt * 16 + aColB]);
    }

    const __half* xrow = g_xh + ((size_t)(n * CC + c0 + tid)) * PP + p0;
    int wp = tid >> 3, wk = (tid & 7) * 8;
    size_t wbase = ((size_t)n * PP + p0 + wp) * KK + wk;

#define VISSUE(ci, b) do {                                                     \
        const __half* _xp = xrow + (ci) * 16;                                  \
        cpa16(s2u32(&xsF[b][tid][0]), _xp);                                    \
        cpa16(s2u32(&xsF[b][tid][8]), _xp + 8);                                \
        cpa16(s2u32(&wsF[b][wp][wk]), g_w2f + wbase + (size_t)(ci) * 16 * KK); \
    } while (0)

    float d[4][4][4] = {};

    VISSUE(0, 0); CP_COMMIT();
    VISSUE(1, 1); CP_COMMIT();
    for (int i = 0; i < nch; i++) {
        int b = i % 3;
        if (i + 2 < nch) { VISSUE(i + 2, (i + 2) % 3); CP_COMMIT(); }
        if (i + 2 < nch) CP_WAIT(2);
        else if (i + 1 < nch) CP_WAIT(1);
        else CP_WAIT(0);
        __syncthreads();
        uint32_t bf[8];
        LDSM4(bf[0], bf[1], bf[2], bf[3], bAF0[b]);
        LDSM4(bf[4], bf[5], bf[6], bf[7], bAF1[b]);
#pragma unroll
        for (int mt = 0; mt < 4; mt++) {
            uint32_t af[4];
            LDSM4T(af[0], af[1], af[2], af[3], aAF[b][mt]);
#pragma unroll
            for (int ng = 0; ng < 4; ng++)
                MMAH(d[mt][ng], af, bf[ng * 2], bf[ng * 2 + 1]);
        }
        __syncthreads();
    }
    int grp = lane >> 2, q = lane & 3;
#pragma unroll
    for (int mt = 0; mt < 4; mt++)
#pragma unroll
        for (int ng = 0; ng < 4; ng++) {
            int k = mt * 16 + grp;
            int c = c0 + warp * 32 + ng * 8 + q * 2;
            size_t o = (((size_t)sp * NN + n) * KK + k) * CC + c;
            *reinterpret_cast<float2*>(&g_vp[o]) =
                make_float2(d[mt][ng][0], d[mt][ng][1]);
            *reinterpret_cast<float2*>(&g_vp[o + 8 * CC]) =
                make_float2(d[mt][ng][2], d[mt][ng][3]);
        }
}

// ---------------- kernel E: reduce partials + residual + intra L2 ----------
__global__ __launch_bounds__(256) void k_norm1(const float* __restrict__ cent,
                                               float* __restrict__ out) {
    __shared__ float red[8];
    __shared__ float stot;
    int k = blockIdx.x, n = blockIdx.y, tid = threadIdx.x;
    int lane = tid & 31, wrp = tid >> 5;
    float wsum = 0.f;
#pragma unroll
    for (int t = 0; t < NPT; t++) wsum += g_wsp[(n * NPT + t) * KK + k];

    float t1a = 0.f, t1b = 0.f;
#pragma unroll
    for (int s = 0; s < NSPLIT; s++) {
        size_t b = (((size_t)s * NN + n) * KK + k) * CC;
        t1a += g_vp[b + tid];
        t1b += g_vp[b + tid + 256];
    }
    size_t base = (size_t)n * KC + (size_t)k * CC;
    float v1 = t1a - wsum * cent[k * CC + tid];
    float v2 = t1b - wsum * cent[k * CC + tid + 256];
    float v = v1 * v1 + v2 * v2;
#pragma unroll
    for (int o = 16; o > 0; o >>= 1) v += __shfl_xor_sync(0xffffffffu, v, o);
    if (lane == 0) red[wrp] = v;
    __syncthreads();
    if (tid == 0) {
        stot = red[0] + red[1] + red[2] + red[3]
             + red[4] + red[5] + red[6] + red[7];
    }
    __syncthreads();
    float tot = stot;
    float inv = 1.f / fmaxf(sqrtf(tot), 1e-12f);
    out[base + tid]       = v1 * inv;
    out[base + tid + 256] = v2 * inv;
    if (tid == 0) g_gpart[n * KK + k] = tot * inv * inv;
}

// ---------------- kernel F: global L2 normalize (float4) --------------------
__global__ __launch_bounds__(256) void k_norm2(float* __restrict__ out) {
    __shared__ float ginv;
    size_t i4 = ((size_t)blockIdx.x * 256 + threadIdx.x) * 4;
    int n = (int)(i4 >> 15);                   // 32768 elements per n
    int lane = threadIdx.x & 31;
    if (threadIdx.x < 32) {
        float t = g_gpart[n * KK + lane] + g_gpart[n * KK + lane + 32];
#pragma unroll
        for (int o = 16; o > 0; o >>= 1) t += __shfl_xor_sync(0xffffffffu, t, o);
        if (lane == 0) ginv = 1.f / fmaxf(sqrtf(t), 1e-12f);
    }
    __syncthreads();
    float g = ginv;
    float4 v = *reinterpret_cast<float4*>(out + i4);
    v.x *= g; v.y *= g; v.z *= g; v.w *= g;
    *reinterpret_cast<float4*>(out + i4) = v;
}

// ---------------- launch -----------------------------------------------------
extern "C" void kernel_launch(void* const* d_in, const int* in_sizes, int n_in,
                              void* d_out, int out_size) {
    const float* x      = (const float*)d_in[0];
    const float* conv_w = (const float*)d_in[1];
    const float* attn_w = (const float*)d_in[2];
    const float* attn_b = (const float*)d_in[3];
    const float* cent   = (const float*)d_in[4];
    float* out = (float*)d_out;
    (void)in_sizes; (void)n_in; (void)out_size;

    k_transpose<<<(CC * KK + 255) / 256, 256>>>(conv_w);
    k_assign_mma<<<dim3(NPT, NN), 128>>>(x, attn_w, attn_b);
    k_vlad_mma<<<dim3(4, NN, NSPLIT), 128>>>(x);
    k_norm1<<<dim3(KK, NN), 256>>>(cent, out);
    k_norm2<<<(NN * KC) / 1024, 256>>>(out);
}